// round 14
// baseline (speedup 1.0000x reference)
#include <cuda_runtime.h>
#include <cuda_fp16.h>
#include <math.h>
#include <stdint.h>

// Problem constants: B=8, S=1024, C=512, H=8, DH=64
namespace {
constexpr int kB  = 8;
constexpr int kS  = 1024;
constexpr int kC  = 512;
constexpr int kH  = 8;
constexpr int kDH = 64;
constexpr int kM  = kB * kS;   // 8192 rows
}

// Scratch (allocation-free device globals), all fp16.
__device__ __half g_xh[kM * kC];        // x converted
__device__ __half g_wh[4 * kC * kC];    // Wq,Wk,Wv,Wo converted
__device__ __half g_q[kM * kC];
__device__ __half g_k[kM * kC];
__device__ __half g_v[kM * kC];
__device__ __half g_ctx[kM * kC];

// ===========================================================================
// Helpers (base sm_103 target; tcgen05 is ptxas-rejected on this harness)
// ===========================================================================
__device__ __forceinline__ uint32_t smem_u32(const void* p) {
    uint32_t a;
    asm("{ .reg .u64 t; cvta.to.shared.u64 t, %1; cvt.u32.u64 %0, t; }"
        : "=r"(a) : "l"(p));
    return a;
}

__device__ __forceinline__ uint32_t f2h2(float lo, float hi) {
    __half2 h = __float22half2_rn(make_float2(lo, hi));
    return *reinterpret_cast<uint32_t*>(&h);
}

__device__ __forceinline__ void cp_async16(uint32_t dst, const void* src) {
    asm volatile("cp.async.cg.shared.global [%0], [%1], 16;"
                 :: "r"(dst), "l"(src));
}
#define CP_COMMIT() asm volatile("cp.async.commit_group;" ::: "memory")
#define CP_WAIT1()  asm volatile("cp.async.wait_group 1;" ::: "memory")

__device__ __forceinline__ void ldmatrix_x4(uint32_t& r0, uint32_t& r1,
                                            uint32_t& r2, uint32_t& r3,
                                            uint32_t addr) {
    asm volatile("ldmatrix.sync.aligned.m8n8.x4.shared.b16 {%0,%1,%2,%3}, [%4];"
                 : "=r"(r0), "=r"(r1), "=r"(r2), "=r"(r3) : "r"(addr));
}

__device__ __forceinline__ void ldmatrix_x4_trans(uint32_t& r0, uint32_t& r1,
                                                  uint32_t& r2, uint32_t& r3,
                                                  uint32_t addr) {
    asm volatile("ldmatrix.sync.aligned.m8n8.x4.trans.shared.b16 {%0,%1,%2,%3}, [%4];"
                 : "=r"(r0), "=r"(r1), "=r"(r2), "=r"(r3) : "r"(addr));
}

// D(16x8) += A(16x16) * B(16x8), f16 inputs, fp32 accumulate.
__device__ __forceinline__ void mma_f16(float* c, uint32_t a0, uint32_t a1,
                                        uint32_t a2, uint32_t a3,
                                        uint32_t b0, uint32_t b1) {
    asm volatile(
        "mma.sync.aligned.m16n8k16.row.col.f32.f16.f16.f32 "
        "{%0,%1,%2,%3}, {%4,%5,%6,%7}, {%8,%9}, {%0,%1,%2,%3};"
        : "+f"(c[0]), "+f"(c[1]), "+f"(c[2]), "+f"(c[3])
        : "r"(a0), "r"(a1), "r"(a2), "r"(a3), "r"(b0), "r"(b1));
}

// ===========================================================================
// fp32 -> fp16 pre-convert: x (kM*kC) and 4 weight matrices (kC*kC each).
// ===========================================================================
struct CvtArgs { const float* src[5]; };

namespace {
constexpr int NX4 = kM * kC / 4;   // float4 count of x
constexpr int NW4 = kC * kC / 4;   // float4 count of one W
}

__global__ void __launch_bounds__(256)
convert_kernel(CvtArgs a)
{
    int i = blockIdx.x * 256 + threadIdx.x;   // float4 index
    const float* src;
    __half* dst;
    int off;
    if (i < NX4) {
        src = a.src[0]; dst = g_xh; off = i;
    } else {
        int r = (i - NX4) >> 16;              // / NW4 (65536)
        off   = (i - NX4) & (NW4 - 1);
        src = a.src[1 + r]; dst = g_wh + r * kC * kC;
    }
    float4 v = ((const float4*)src)[off];
    uint2 w;
    w.x = f2h2(v.x, v.y);
    w.y = f2h2(v.z, v.w);
    *(uint2*)&dst[off * 4] = w;
}

// ===========================================================================
// f16 mma.sync GEMM core: acc[m,n] = sum_k X[m,k]*W[n,k]
// CTA 128x128, BK=64 (4 x k16 per slab, 8 slabs -> 8 barriers), 8 warps
// 32(m) x 64(n). 3-stage cp.async pipeline (2 slabs in flight).
// Fragment double-buffering: LDSMs for step ks+1 issued before MMAs of ks.
// smem pitch 72 halves (144 B): 16B-aligned rows, 4r-distinct banks ->
// conflict-free ldmatrix. 3 stages x 36864 B = 110592 B -> 2 CTAs/SM.
// ===========================================================================
namespace {
constexpr int GP = 72;                          // pitch in halves
constexpr int GEMM_MAT_B   = 128 * GP * 2;      // 18432 B per matrix
constexpr int GEMM_STAGE_B = 2 * GEMM_MAT_B;    // 36864 B per stage
constexpr int GEMM_SMEM    = 3 * GEMM_STAGE_B;  // 110592 B
constexpr int NSLAB = kC / 64;                  // 8
}

#define GEMM_LDFRAG(buf, ko) do {                                            \
    _Pragma("unroll")                                                        \
    for (int t = 0; t < 2; t++)                                              \
        ldmatrix_x4(a[buf][t][0], a[buf][t][1], a[buf][t][2], a[buf][t][3],  \
                    a_addr[t] + (ko));                                       \
    _Pragma("unroll")                                                        \
    for (int jj = 0; jj < 4; jj++) {                                         \
        uint32_t r0, r1, r2, r3;                                             \
        ldmatrix_x4(r0, r1, r2, r3, b_addr[jj] + (ko));                      \
        b[buf][2 * jj][0] = r0;      b[buf][2 * jj][1] = r1;                 \
        b[buf][2 * jj + 1][0] = r2;  b[buf][2 * jj + 1][1] = r3;             \
    }                                                                        \
} while (0)

// Runs the mainloop; leaves results in acc[2][8][4].
__device__ __forceinline__ void gemm_mainloop(
    const __half* __restrict__ X, const __half* __restrict__ W,
    int m0, int n0, __half* dsm, float acc[2][8][4])
{
    const int tid = threadIdx.x;
    const int lid = tid & 31;
    const int wid = tid >> 5;
    const int wm  = (wid >> 1) * 32;
    const int wn  = (wid & 1) * 64;

    // loader: 4 16B-chunks per matrix per thread per slab (2 threads/row)
    const int lrow = tid >> 1;             // 0..127
    const int lc   = (tid & 1) * 32;       // half offset (0 or 32)

    const uint32_t sAu = smem_u32(dsm);                // stage 0 A
    const uint32_t sBu = sAu + GEMM_MAT_B;             // stage 0 B

    const uint32_t dA = sAu + (lrow * GP + lc) * 2;
    const uint32_t dB = sBu + (lrow * GP + lc) * 2;
    const __half* gA = X + (size_t)(m0 + lrow) * kC + lc;
    const __half* gB = W + (size_t)(n0 + lrow) * kC + lc;

    // ldmatrix fragment addresses (stage 0)
    uint32_t a_addr[2], b_addr[4];
#pragma unroll
    for (int t = 0; t < 2; t++)
        a_addr[t] = sAu + (wm + 16 * t + (lid & 15)) * (GP * 2) + ((lid >> 4) << 4);
#pragma unroll
    for (int jj = 0; jj < 4; jj++)
        b_addr[jj] = sBu + (wn + 16 * jj + ((lid >> 4) << 3) + (lid & 7)) * (GP * 2)
                   + (((lid >> 3) & 1) << 4);

#pragma unroll
    for (int t = 0; t < 2; t++)
#pragma unroll
        for (int j = 0; j < 8; j++)
#pragma unroll
            for (int c = 0; c < 4; c++) acc[t][j][c] = 0.f;

    // prologue: issue slabs 0,1 into stages 0,1 (one commit-group each)
#pragma unroll
    for (int p = 0; p < 2; p++) {
        const uint32_t so = (uint32_t)p * GEMM_STAGE_B;
        const int k0 = p * 64;
#pragma unroll
        for (int c = 0; c < 4; c++) {
            cp_async16(dA + so + c * 16, gA + k0 + c * 8);
            cp_async16(dB + so + c * 16, gB + k0 + c * 8);
        }
        CP_COMMIT();
    }

#pragma unroll 1
    for (int s = 0; s < NSLAB; s++) {
        CP_WAIT1();            // slab s complete (slab s+1 may stay in flight)
        __syncthreads();       // visibility + all warps done with compute s-1

        if (s + 2 < NSLAB) {   // issue slab s+2 into stage (s+2)%3
            const uint32_t so = (uint32_t)((s + 2) % 3) * GEMM_STAGE_B;
            const int k0 = (s + 2) * 64;
#pragma unroll
            for (int c = 0; c < 4; c++) {
                cp_async16(dA + so + c * 16, gA + k0 + c * 8);
                cp_async16(dB + so + c * 16, gB + k0 + c * 8);
            }
        }
        CP_COMMIT();           // always commit (fixed group numbering)

        const uint32_t soff = (uint32_t)(s % 3) * GEMM_STAGE_B;

        // fragment-pipelined 4 k16 steps: LDSM(ks+1) issued before MMA(ks)
        uint32_t a[2][2][4];
        uint32_t b[2][8][2];
        GEMM_LDFRAG(0, soff);
#pragma unroll
        for (int ks = 0; ks < 4; ks++) {
            const int cur = ks & 1;
            if (ks < 3) {
                const int nxt = cur ^ 1;
                const uint32_t ko = soff + (ks + 1) * 32;
                GEMM_LDFRAG(nxt, ko);
            }
#pragma unroll
            for (int t = 0; t < 2; t++)
#pragma unroll
                for (int j = 0; j < 8; j++)
                    mma_f16(acc[t][j],
                            a[cur][t][0], a[cur][t][1], a[cur][t][2], a[cur][t][3],
                            b[cur][j][0], b[cur][j][1]);
        }
    }
}

// QKV fused GEMM: z selects (W, bias, half-out). X = g_xh.
struct QKVArgs { const float *b0, *b1, *b2; __half *o0, *o1, *o2; };

__global__ void __launch_bounds__(256, 2)
gemm_qkv_kernel(QKVArgs args)
{
    extern __shared__ __half dsm[];
    const int z = blockIdx.z;
    const float* bias = (z == 0) ? args.b0 : (z == 1) ? args.b1 : args.b2;
    __half* out       = (z == 0) ? args.o0 : (z == 1) ? args.o1 : args.o2;
    const int m0 = blockIdx.y * 128;
    const int n0 = blockIdx.x * 128;

    float acc[2][8][4];
    gemm_mainloop(g_xh, g_wh + (size_t)z * kC * kC, m0, n0, dsm, acc);

    const int lid = threadIdx.x & 31;
    const int wid = threadIdx.x >> 5;
    const int wm  = (wid >> 1) * 32;
    const int wn  = (wid & 1) * 64;
    const int g   = lid >> 2;
    const int cp  = (lid & 3) * 2;
#pragma unroll
    for (int t = 0; t < 2; t++) {
        const int r0 = m0 + wm + 16 * t + g;
#pragma unroll
        for (int j = 0; j < 8; j++) {
            const int n = n0 + wn + 8 * j + cp;
            const float bx = bias[n], by = bias[n + 1];
            *(uint32_t*)&out[(size_t)r0 * kC + n] =
                f2h2(acc[t][j][0] + bx, acc[t][j][1] + by);
            *(uint32_t*)&out[(size_t)(r0 + 8) * kC + n] =
                f2h2(acc[t][j][2] + bx, acc[t][j][3] + by);
        }
    }
}

// Output GEMM: X = g_ctx (half), W = Wo (converted), out fp32 + bias + skip.
__global__ void __launch_bounds__(256, 2)
gemm_o_kernel(const float* __restrict__ bias, const float* __restrict__ skip,
              float* __restrict__ out)
{
    extern __shared__ __half dsm[];
    const int m0 = blockIdx.y * 128;
    const int n0 = blockIdx.x * 128;

    float acc[2][8][4];
    gemm_mainloop(g_ctx, g_wh + (size_t)3 * kC * kC, m0, n0, dsm, acc);

    const int lid = threadIdx.x & 31;
    const int wid = threadIdx.x >> 5;
    const int wm  = (wid >> 1) * 32;
    const int wn  = (wid & 1) * 64;
    const int g   = lid >> 2;
    const int cp  = (lid & 3) * 2;
#pragma unroll
    for (int t = 0; t < 2; t++) {
        const int r0 = m0 + wm + 16 * t + g;
#pragma unroll
        for (int j = 0; j < 8; j++) {
            const int n = n0 + wn + 8 * j + cp;
            const float bx = bias[n], by = bias[n + 1];
            float2 s0 = *(const float2*)&skip[(size_t)r0 * kC + n];
            float2 s1 = *(const float2*)&skip[(size_t)(r0 + 8) * kC + n];
            *(float2*)&out[(size_t)r0 * kC + n] =
                make_float2(acc[t][j][0] + bx + s0.x, acc[t][j][1] + by + s0.y);
            *(float2*)&out[(size_t)(r0 + 8) * kC + n] =
                make_float2(acc[t][j][2] + bx + s1.x, acc[t][j][3] + by + s1.y);
        }
    }
}

// ===========================================================================
// Tensor-core flash attention (f16 mma.sync, fp32 accumulate).
// CTA = 128 queries x one (b,h); 8 warps x 16 query rows; key tiles of 64.
// Q fragments hoisted to registers. P stays in registers (C->A repack).
// K/V tiles: 3-stage cp.async pipeline, wait_group 1, always-commit.
// smem (dynamic): 3 stages x (Ks[64][72] | Vs[64][72]) = 55296 B.
// ===========================================================================
namespace {
constexpr int PQH = 72;
constexpr int ATTN_TILE_B = 128 * PQH * 2;     // 18432 B per stage (K+V)
constexpr int ATTN_SMEM   = 3 * ATTN_TILE_B;   // 55296 B
constexpr int NTILE = kS / 64;                 // 16
}

__global__ void __launch_bounds__(256, 2)
attn_tc_kernel()
{
    extern __shared__ __half sm[];

    const int tid = threadIdx.x;
    const int lid = tid & 31;
    const int wid = tid >> 5;
    const int b   = blockIdx.z;
    const int h   = blockIdx.y;
    const int q0  = blockIdx.x * 128;

    const __half* Qg = g_q + (size_t)(b * kS + q0) * kC + h * kDH;
    const __half* Kg = g_k + (size_t)(b * kS) * kC + h * kDH;
    const __half* Vg = g_v + (size_t)(b * kS) * kC + h * kDH;

    // --- Stage Q through smem once; extract loop-invariant A fragments ---
#pragma unroll
    for (int t = 0; t < 4; t++) {
        int idx = tid + t * 256;          // 0..1023 16B-chunks
        int row = idx >> 3;               // 0..127
        int c8  = (idx & 7) * 8;
        *(uint4*)&sm[row * PQH + c8] = *(const uint4*)(Qg + (size_t)row * kC + c8);
    }
    __syncthreads();
    uint32_t qf[4][4];
    {
        const uint32_t aq = smem_u32(sm)
            + (wid * 16 + (lid & 15)) * (PQH * 2) + ((lid >> 4) << 4);
#pragma unroll
        for (int ks = 0; ks < 4; ks++)
            ldmatrix_x4(qf[ks][0], qf[ks][1], qf[ks][2], qf[ks][3], aq + ks * 32);
    }
    __syncthreads();   // done with Q staging; smem now K/V stages

    // cp.async destinations (stage 0): K rows 0..63, V rows 64..127
    const int lrow = tid >> 3;            // 0..31
    const int lc8  = (tid & 7) * 8;
    const uint32_t smu = smem_u32(sm);
    const uint32_t dK0 = smu + (lrow * PQH + lc8) * 2;
    const uint32_t dK1 = dK0 + 32 * PQH * 2;
    const uint32_t dV0 = smu + ((64 + lrow) * PQH + lc8) * 2;
    const uint32_t dV1 = dV0 + 32 * PQH * 2;
    const __half* gK0 = Kg + (size_t)lrow * kC + lc8;
    const __half* gK1 = Kg + (size_t)(32 + lrow) * kC + lc8;
    const __half* gV0 = Vg + (size_t)lrow * kC + lc8;
    const __half* gV1 = Vg + (size_t)(32 + lrow) * kC + lc8;

    // fragment addresses (stage 0)
    uint32_t bk[4], bvb[4];
#pragma unroll
    for (int jj = 0; jj < 4; jj++) {
        bk[jj] = smu
            + (16 * jj + ((lid >> 4) << 3) + (lid & 7)) * (PQH * 2)
            + (((lid >> 3) & 1) << 4);
        bvb[jj] = smu + 64 * PQH * 2
            + ((((lid >> 3) & 1) << 3) + (lid & 7)) * (PQH * 2)
            + (((lid >> 4) + 2 * jj) << 4);
    }

    float m_i[2] = {-INFINITY, -INFINITY};
    float l_i[2] = {0.f, 0.f};
    float accO[8][4];
#pragma unroll
    for (int j = 0; j < 8; j++)
#pragma unroll
        for (int c = 0; c < 4; c++) accO[j][c] = 0.f;
    const float cexp = 0.125f * 1.4426950408889634f;  // scale * log2(e)

    const int pr = wid * 16 + (lid >> 2);
    const int pc = (lid & 3) * 2;

    // prologue: issue K/V tiles 0,1 into stages 0,1
#pragma unroll
    for (int p = 0; p < 2; p++) {
        const uint32_t so = (uint32_t)p * ATTN_TILE_B;
        const size_t go = (size_t)p * 64 * kC;
        cp_async16(dK0 + so, gK0 + go);
        cp_async16(dK1 + so, gK1 + go);
        cp_async16(dV0 + so, gV0 + go);
        cp_async16(dV1 + so, gV1 + go);
        CP_COMMIT();
    }

#pragma unroll 1
    for (int i = 0; i < NTILE; i++) {
        CP_WAIT1();            // group i (tile i) complete
        __syncthreads();       // all warps done with compute i-1

        if (i + 2 < NTILE) {   // issue tile i+2 into stage (i+2)%3
            const uint32_t so = (uint32_t)((i + 2) % 3) * ATTN_TILE_B;
            const size_t go = (size_t)(i + 2) * 64 * kC;
            cp_async16(dK0 + so, gK0 + go);
            cp_async16(dK1 + so, gK1 + go);
            cp_async16(dV0 + so, gV0 + go);
            cp_async16(dV1 + so, gV1 + go);
        }
        CP_COMMIT();           // always commit

        const uint32_t boff = (uint32_t)(i % 3) * ATTN_TILE_B;

        // S = Q K^T   (4 k16 steps over d=64)
        float s[8][4];
#pragma unroll
        for (int j = 0; j < 8; j++)
#pragma unroll
            for (int c = 0; c < 4; c++) s[j][c] = 0.f;
#pragma unroll
        for (int ks = 0; ks < 4; ks++) {
            uint32_t bf[8][2];
#pragma unroll
            for (int jj = 0; jj < 4; jj++) {
                uint32_t r0, r1, r2, r3;
                ldmatrix_x4(r0, r1, r2, r3, bk[jj] + boff + ks * 32);
                bf[2 * jj][0] = r0;  bf[2 * jj][1] = r1;
                bf[2 * jj + 1][0] = r2;  bf[2 * jj + 1][1] = r3;
            }
#pragma unroll
            for (int j = 0; j < 8; j++)
                mma_f16(s[j], qf[ks][0], qf[ks][1], qf[ks][2], qf[ks][3],
                        bf[j][0], bf[j][1]);
        }

        // online softmax (half 0: row pr; half 1: row pr+8)
#pragma unroll
        for (int hf = 0; hf < 2; hf++) {
            const int c0 = 2 * hf, c1 = 2 * hf + 1;
            float mx = fmaxf(s[0][c0], s[0][c1]);
#pragma unroll
            for (int j = 1; j < 8; j++)
                mx = fmaxf(mx, fmaxf(s[j][c0], s[j][c1]));
            mx = fmaxf(mx, __shfl_xor_sync(0xffffffffu, mx, 1));
            mx = fmaxf(mx, __shfl_xor_sync(0xffffffffu, mx, 2));
            float mnew = fmaxf(m_i[hf], mx);
            float alpha = exp2f((m_i[hf] - mnew) * cexp);
            float rs = 0.f;
#pragma unroll
            for (int j = 0; j < 8; j++) {
                s[j][c0] = exp2f((s[j][c0] - mnew) * cexp);
                s[j][c1] = exp2f((s[j][c1] - mnew) * cexp);
                rs += s[j][c0] + s[j][c1];
            }
            rs += __shfl_xor_sync(0xffffffffu, rs, 1);
            rs += __shfl_xor_sync(0xffffffffu, rs, 2);
            l_i[hf] = l_i[hf] * alpha + rs;
            m_i[hf] = mnew;
#pragma unroll
            for (int j = 0; j < 8; j++) {
                accO[j][c0] *= alpha;
                accO[j][c1] *= alpha;
            }
        }

        // O += P * V : P's A-fragments come straight from S's C-fragments.
#pragma unroll
        for (int ks = 0; ks < 4; ks++) {
            const uint32_t a0 = f2h2(s[2 * ks][0],     s[2 * ks][1]);
            const uint32_t a1 = f2h2(s[2 * ks][2],     s[2 * ks][3]);
            const uint32_t a2 = f2h2(s[2 * ks + 1][0], s[2 * ks + 1][1]);
            const uint32_t a3 = f2h2(s[2 * ks + 1][2], s[2 * ks + 1][3]);
            uint32_t bf[8][2];
#pragma unroll
            for (int jj = 0; jj < 4; jj++) {
                uint32_t r0, r1, r2, r3;
                ldmatrix_x4_trans(r0, r1, r2, r3,
                                  bvb[jj] + boff + ks * 16 * (PQH * 2));
                bf[2 * jj][0] = r0;  bf[2 * jj][1] = r1;
                bf[2 * jj + 1][0] = r2;  bf[2 * jj + 1][1] = r3;
            }
#pragma unroll
            for (int j = 0; j < 8; j++)
                mma_f16(accO[j], a0, a1, a2, a3, bf[j][0], bf[j][1]);
        }
    }

    // normalize + write ctx (fp16)
    {
        const float inv0 = 1.f / l_i[0];
        const float inv1 = 1.f / l_i[1];
        __half* O0 = g_ctx + (size_t)(b * kS + q0 + pr) * kC + h * kDH;
        __half* O1 = O0 + (size_t)8 * kC;
#pragma unroll
        for (int j = 0; j < 8; j++) {
            const int c = 8 * j + pc;
            *(uint32_t*)&O0[c] = f2h2(accO[j][0] * inv0, accO[j][1] * inv0);
            *(uint32_t*)&O1[c] = f2h2(accO[j][2] * inv1, accO[j][3] * inv1);
        }
    }
}

// ---------------------------------------------------------------------------
// Launch
// ---------------------------------------------------------------------------
extern "C" void kernel_launch(void* const* d_in, const int* in_sizes, int n_in,
                              void* d_out, int out_size)
{
    (void)in_sizes; (void)n_in; (void)out_size;
    const float* x    = (const float*)d_in[0];
    const float* skip = (const float*)d_in[1];
    const float* Wq   = (const float*)d_in[2];
    const float* bq   = (const float*)d_in[3];
    const float* Wk   = (const float*)d_in[4];
    const float* bk   = (const float*)d_in[5];
    const float* Wv   = (const float*)d_in[6];
    const float* bv   = (const float*)d_in[7];
    const float* Wo   = (const float*)d_in[8];
    const float* bo   = (const float*)d_in[9];
    float* out = (float*)d_out;

    __half *qb, *kb, *vb;
    cudaGetSymbolAddress((void**)&qb, g_q);
    cudaGetSymbolAddress((void**)&kb, g_k);
    cudaGetSymbolAddress((void**)&vb, g_v);

    cudaFuncSetAttribute(gemm_qkv_kernel,
                         cudaFuncAttributeMaxDynamicSharedMemorySize, GEMM_SMEM);
    cudaFuncSetAttribute(gemm_o_kernel,
                         cudaFuncAttributeMaxDynamicSharedMemorySize, GEMM_SMEM);
    cudaFuncSetAttribute(attn_tc_kernel,
                         cudaFuncAttributeMaxDynamicSharedMemorySize, ATTN_SMEM);

    // 1) convert x + weights to fp16
    CvtArgs ca; ca.src[0] = x; ca.src[1] = Wq; ca.src[2] = Wk;
    ca.src[3] = Wv; ca.src[4] = Wo;
    convert_kernel<<<(NX4 + 4 * NW4) / 256, 256>>>(ca);

    // 2) fused QKV projections (128x128, BK=64, 3-stage, frag-pipelined)
    QKVArgs qkv = { bq, bk, bv, qb, kb, vb };
    gemm_qkv_kernel<<<dim3(kC / 128, kM / 128, 3), 256, GEMM_SMEM>>>(qkv);

    // 3) attention (3-stage pipeline)
    attn_tc_kernel<<<dim3(kS / 128, kH, kB), 256, ATTN_SMEM>>>();

    // 4) output projection + bias + skip
    gemm_o_kernel<<<dim3(kC / 128, kM / 128, 1), 256, GEMM_SMEM>>>(bo, skip, out);
}